// round 4
// baseline (speedup 1.0000x reference)
#include <cuda_runtime.h>

#define S_LEN 128
#define B_SZ  64
#define E_DIM 512
#define PL    160
#define PD    512
#define H_DIM 1024

#define NBLK 128
#define NTHR 256

typedef unsigned long long u64;

// ---------------- persistent scratch (device globals) ----------------
__device__ float2 g_H2T[2][(H_DIM / 2) * B_SZ];              // [buf][k2*64+b]
__device__ float2 g_CTX2T[(PD / 2) * B_SZ];                  // [d2*64+b]
__device__ float2 g_INC2T[(size_t)S_LEN * (E_DIM / 2) * B_SZ];  // [t][k2][b], 16MB
__device__ float  g_Qrow[B_SZ * PD];                         // [b][d]
__device__ unsigned int g_count;
__device__ unsigned int g_release;

// ---------------- packed f32x2 helpers ----------------
__device__ __forceinline__ void ffma2(u64& d, u64 a, u64 b) {
    asm("fma.rn.f32x2 %0, %1, %2, %0;" : "+l"(d) : "l"(a), "l"(b));
}
__device__ __forceinline__ float sum2(u64 v) {
    float2 f;
    f.x = __int_as_float((unsigned)(v & 0xffffffffULL));
    f.y = __int_as_float((unsigned)(v >> 32));
    return f.x + f.y;
}

// ---------------- grid-wide epoch barrier ----------------
__device__ __forceinline__ void gsync(unsigned int epoch) {
    __syncthreads();
    if (threadIdx.x == 0) {
        __threadfence();
        unsigned int arrived = atomicAdd(&g_count, 1u) + 1u;
        if (arrived == (unsigned)NBLK * epoch) {
            atomicExch(&g_release, epoch);
        } else {
            while (*(volatile unsigned int*)&g_release < epoch) {
                __nanosleep(40);
            }
        }
        __threadfence();
    }
    __syncthreads();
}

// ---------------- pre-pass: transpose incoming, broadcast h0, reset barrier ----------------
__global__ void pre_kernel(const float* __restrict__ incoming,
                           const float* __restrict__ h_init) {
    int t = blockIdx.x;   // 0..127
    int tid = threadIdx.x;
    // incoming[t][b][k] -> g_INC2T[t][k2][b]
    for (int idx = tid; idx < (E_DIM / 2) * B_SZ; idx += NTHR) {
        int k2 = idx >> 6, b = idx & 63;
        const float* src = incoming + ((size_t)t * B_SZ + b) * E_DIM + 2 * k2;
        g_INC2T[(size_t)t * ((E_DIM / 2) * B_SZ) + idx] = make_float2(src[0], src[1]);
    }
    // h_init broadcast: block t fills its slice of g_H2T[0]
    {
        int g = t * 256 + tid;           // 128 blocks * 256 = 32768 = (H/2)*B
        int k2 = g >> 6;
        g_H2T[0][g] = make_float2(h_init[2 * k2], h_init[2 * k2 + 1]);
    }
    if (t == 0 && tid == 0) { g_count = 0u; g_release = 0u; }
}

// ---------------- persistent recurrent kernel ----------------
__global__ void __launch_bounds__(NTHR, 1) gru_kernel(
    const float* __restrict__ post,
    const float* __restrict__ wih,
    const float* __restrict__ whh,
    const float* __restrict__ bih,
    const float* __restrict__ bhh,
    const float* __restrict__ wq,
    const float* __restrict__ bq,
    const int* __restrict__ length,
    const int* __restrict__ post_length,
    float* __restrict__ out,
    int write_last)
{
    __shared__ float2 s_x[64][32];               // K-chunk: 64 k2 x 32 b   (16KB)
    __shared__ __align__(16) float s_q[PD];      // attention query
    __shared__ float s_sc[PL];
    __shared__ u64   s_e2[PL];                   // packed {e,e}
    __shared__ float s_stat[2];                  // [0]=max, [1]=1/sum

    const int tid = threadIdx.x;
    const int bx = blockIdx.x;
    const int wid = tid >> 5;
    const int lane = tid & 31;

    // gates-phase constants for this block
    const int g_half  = bx & 1;
    const int g_jbase = (bx >> 1) * 16;
    const int g_j0    = g_jbase + wid * 2;
    const int g_b     = g_half * 32 + lane;
    const int g_len   = length[g_b];

    unsigned int ep = 0;

    for (int t = 0; t < S_LEN; t++) {
        const float2* hcur = g_H2T[t & 1];
        float2* hnext      = g_H2T[(t & 1) ^ 1];

        // ================= Phase 1: Q = h @ wq^T + bq =================
        // 1024 warp-jobs: (d in [0,512), half in {0,1})
        {
            int gw = bx * 8 + wid;
            int d = gw >> 1;
            int half = gw & 1;
            int b = half * 32 + lane;
            const ulonglong2* w2 = (const ulonglong2*)(wq + (size_t)d * H_DIM);
            const u64* hsrc = (const u64*)hcur;
            u64 a0 = 0ull, a1 = 0ull;
#pragma unroll 4
            for (int k4 = 0; k4 < H_DIM / 4; k4++) {
                ulonglong2 w = w2[k4];
                u64 xa = hsrc[(2 * k4) * B_SZ + b];
                u64 xb = hsrc[(2 * k4 + 1) * B_SZ + b];
                ffma2(a0, w.x, xa);
                ffma2(a1, w.y, xb);
            }
            g_Qrow[(size_t)b * PD + d] = sum2(a0) + sum2(a1) + bq[d];
        }
        ep++; gsync(ep);

        // ================= Phase 2: attention (blocks 0..63 = batch) =================
        if (bx < B_SZ) {
            const int b = bx;
            s_q[tid] = g_Qrow[(size_t)b * PD + tid];
            s_q[tid + 256] = g_Qrow[(size_t)b * PD + 256 + tid];
            __syncthreads();

            int pl = post_length[b];
            const ulonglong2* qq = (const ulonglong2*)s_q;
            // scores: warp per p, lanes along d (coalesced)
            for (int p = wid; p < PL; p += 8) {
                const ulonglong2* pp =
                    (const ulonglong2*)(post + ((size_t)p * B_SZ + b) * PD);
                u64 a0 = 0ull, a1 = 0ull;
#pragma unroll 4
                for (int i = lane; i < PD / 4; i += 32) {
                    ulonglong2 pv = pp[i];
                    ulonglong2 qv = qq[i];
                    ffma2(a0, pv.x, qv.x);
                    ffma2(a1, pv.y, qv.y);
                }
                float s = sum2(a0) + sum2(a1);
#pragma unroll
                for (int o = 16; o > 0; o >>= 1)
                    s += __shfl_xor_sync(0xffffffffu, s, o);
                if (lane == 0) s_sc[p] = (p < pl) ? s : -1e30f;
            }
            __syncthreads();

            if (tid < 32) {
                float m = -1e30f;
                for (int p = tid; p < PL; p += 32) m = fmaxf(m, s_sc[p]);
#pragma unroll
                for (int o = 16; o > 0; o >>= 1)
                    m = fmaxf(m, __shfl_xor_sync(0xffffffffu, m, o));
                if (tid == 0) s_stat[0] = m;
            }
            __syncthreads();
            if (tid < PL) {
                float e = __expf(s_sc[tid] - s_stat[0]);
                s_sc[tid] = e;
                float2 ee = make_float2(e, e);
                s_e2[tid] = *(u64*)&ee;
            }
            __syncthreads();
            if (tid < 32) {
                float s = 0.f;
                for (int p = tid; p < PL; p += 32) s += s_sc[p];
#pragma unroll
                for (int o = 16; o > 0; o >>= 1)
                    s += __shfl_xor_sync(0xffffffffu, s, o);
                if (tid == 0) s_stat[1] = 1.f / s;
            }
            __syncthreads();

            // context: thread = d-pair (d = 2*tid); packed FFMA2; write transposed
            {
                const u64* pb = (const u64*)post + (size_t)b * (PD / 2) + tid;
                u64 c2 = 0ull;
#pragma unroll 4
                for (int p = 0; p < PL; p++)
                    ffma2(c2, s_e2[p], pb[(size_t)p * (B_SZ * PD / 2)]);
                float inv = s_stat[1];
                float lo = __int_as_float((unsigned)(c2 & 0xffffffffULL));
                float hi = __int_as_float((unsigned)(c2 >> 32));
                g_CTX2T[tid * B_SZ + b] = make_float2(lo * inv, hi * inv);
            }
        }
        ep++; gsync(ep);

        // ================= Phase 3: GRU gates =================
        // block = (b-half, 16 j's); warp = 2 j's; lanes = 32 batches of half
        {
            u64 acc[2][2][3];
#pragma unroll
            for (int p = 0; p < 2; p++)
#pragma unroll
                for (int jj = 0; jj < 2; jj++)
#pragma unroll
                    for (int g = 0; g < 3; g++) acc[p][jj][g] = 0ull;

#pragma unroll
            for (int part = 0; part < 2; part++) {
                const float* W = part ? whh : wih;
                const ulonglong2* wr[2][3];
#pragma unroll
                for (int jj = 0; jj < 2; jj++)
#pragma unroll
                    for (int g = 0; g < 3; g++)
                        wr[jj][g] = (const ulonglong2*)(W +
                            ((size_t)(g * H_DIM) + g_j0 + jj) * (size_t)1024);

                for (int chunk = 0; chunk < 8; chunk++) {
                    const float2* src;
                    if (part) src = hcur + chunk * 64 * B_SZ;
                    else if (chunk < 4)
                        src = g_INC2T + ((size_t)t * (E_DIM / 2) + chunk * 64) * B_SZ;
                    else
                        src = g_CTX2T + (size_t)(chunk - 4) * 64 * B_SZ;

                    // cooperative chunk load: 64 k2 x 32 b
#pragma unroll
                    for (int i = 0; i < 8; i++) {
                        int row = (tid >> 5) + i * 8;
                        s_x[row][lane] = src[row * B_SZ + g_half * 32 + lane];
                    }
                    __syncthreads();

                    const int kw = chunk * 32;
#pragma unroll 4
                    for (int k4 = 0; k4 < 32; k4++) {
                        u64 xa = *(const u64*)&s_x[2 * k4][lane];
                        u64 xb = *(const u64*)&s_x[2 * k4 + 1][lane];
#pragma unroll
                        for (int jj = 0; jj < 2; jj++)
#pragma unroll
                            for (int g = 0; g < 3; g++) {
                                ulonglong2 w = wr[jj][g][kw + k4];
                                ffma2(acc[part][jj][g], w.x, xa);
                                ffma2(acc[part][jj][g], w.y, xb);
                            }
                    }
                    __syncthreads();
                }
            }

            // combine + activations + writes
            float2 hprev2 = hcur[(g_j0 >> 1) * B_SZ + g_b];
            float hp[2] = { hprev2.x, hprev2.y };
            float hn[2];
#pragma unroll
            for (int jj = 0; jj < 2; jj++) {
                int j = g_j0 + jj;
                float ir  = sum2(acc[0][jj][0]) + bih[j];
                float iz  = sum2(acc[0][jj][1]) + bih[H_DIM + j];
                float inn = sum2(acc[0][jj][2]) + bih[2 * H_DIM + j];
                float hr  = sum2(acc[1][jj][0]) + bhh[j];
                float hz  = sum2(acc[1][jj][1]) + bhh[H_DIM + j];
                float hnn = sum2(acc[1][jj][2]) + bhh[2 * H_DIM + j];
                float r = 1.f / (1.f + __expf(-(ir + hr)));
                float z = 1.f / (1.f + __expf(-(iz + hz)));
                float n = tanhf(inn + r * hnn);
                hn[jj] = (1.f - z) * n + z * hp[jj];
                if (g_len <= t) hn[jj] = 0.f;
            }
            float2 hv = make_float2(hn[0], hn[1]);
            hnext[(g_j0 >> 1) * B_SZ + g_b] = hv;
            *(float2*)&out[((size_t)t * B_SZ + g_b) * H_DIM + g_j0] = hv;
            if (write_last && t == S_LEN - 1) {
                *(float2*)&out[(size_t)S_LEN * B_SZ * H_DIM +
                               (size_t)g_b * H_DIM + g_j0] = hv;
            }
        }
        ep++; gsync(ep);
    }
}

// ---------------- launch ----------------
extern "C" void kernel_launch(void* const* d_in, const int* in_sizes, int n_in,
                              void* d_out, int out_size) {
    const float* incoming    = (const float*)d_in[0];
    const float* post        = (const float*)d_in[1];
    const float* h_init      = (const float*)d_in[2];
    const float* wih         = (const float*)d_in[3];
    const float* whh         = (const float*)d_in[4];
    const float* bih         = (const float*)d_in[5];
    const float* bhh         = (const float*)d_in[6];
    const float* wq          = (const float*)d_in[7];
    const float* bq          = (const float*)d_in[8];
    const int*   length      = (const int*)d_in[9];
    const int*   post_length = (const int*)d_in[10];
    float* out = (float*)d_out;

    int write_last = (out_size >= S_LEN * B_SZ * H_DIM + B_SZ * H_DIM) ? 1 : 0;

    pre_kernel<<<S_LEN, NTHR>>>(incoming, h_init);
    gru_kernel<<<NBLK, NTHR>>>(post, wih, whh, bih, bhh, wq, bq,
                               length, post_length, out, write_last);
}

// round 5
// speedup vs baseline: 1.5259x; 1.5259x over previous
#include <cuda_runtime.h>

#define S_LEN 128
#define B_SZ  64
#define E_DIM 512
#define PL    160
#define PD    512
#define H_DIM 1024

#define NBLK 128
#define NTHR 512

typedef unsigned long long u64;

// ---------------- persistent scratch (device globals) ----------------
__device__ __align__(16) float2 g_H2T[2][(H_DIM / 2) * B_SZ];     // [buf][k2*64+b]
__device__ __align__(16) float2 g_CTX2T[(PD / 2) * B_SZ];         // [d2*64+b]
__device__ __align__(16) float2 g_INC2T[(size_t)S_LEN * (E_DIM / 2) * B_SZ]; // [t][k2][b]
__device__ float  g_Qrow[B_SZ * PD];                              // [b][d]
__device__ unsigned int g_count;
__device__ unsigned int g_release;

// ---------------- smem layout (dynamic) ----------------
#define OFF_W    0          // float [2][3][16][128]  = 49152 B   (gates W double buffer)
#define OFF_X    49152      // float2 [2][64][32]     = 32768 B   (gates x double buffer)
#define OFF_Q    81920      // float [512]
#define OFF_SC   83968      // float [160]
#define OFF_E2   84608      // u64   [160]
#define OFF_STAT 85888      // float [2]
#define SMEM_SZ  86016
// phase-1 partials alias the gates W region (phases separated by gsync)
#define OFF_PART 0          // float [16][4][32] = 8192 B

// ---------------- packed f32x2 helpers ----------------
__device__ __forceinline__ void ffma2(u64& d, u64 a, u64 b) {
    asm("fma.rn.f32x2 %0, %1, %2, %0;" : "+l"(d) : "l"(a), "l"(b));
}
__device__ __forceinline__ float sum2(u64 v) {
    float lo = __int_as_float((unsigned)(v & 0xffffffffULL));
    float hi = __int_as_float((unsigned)(v >> 32));
    return lo + hi;
}

// ---------------- cp.async helpers ----------------
__device__ __forceinline__ void cpa16(void* s, const void* g) {
    unsigned saddr = (unsigned)__cvta_generic_to_shared(s);
    asm volatile("cp.async.ca.shared.global [%0], [%1], 16;" :: "r"(saddr), "l"(g));
}

// ---------------- grid-wide epoch barrier ----------------
__device__ __forceinline__ void gsync(unsigned int epoch) {
    __syncthreads();
    if (threadIdx.x == 0) {
        __threadfence();
        unsigned int arrived = atomicAdd(&g_count, 1u) + 1u;
        if (arrived == (unsigned)NBLK * epoch) {
            atomicExch(&g_release, epoch);
        } else {
            while (*(volatile unsigned int*)&g_release < epoch) {
                __nanosleep(40);
            }
        }
        __threadfence();
    }
    __syncthreads();
}

// ---------------- pre-pass: transpose incoming, broadcast h0, reset barrier ----------------
__global__ void pre_kernel(const float* __restrict__ incoming,
                           const float* __restrict__ h_init) {
    int t = blockIdx.x;   // 0..127
    int tid = threadIdx.x;
    for (int idx = tid; idx < (E_DIM / 2) * B_SZ; idx += 256) {
        int k2 = idx >> 6, b = idx & 63;
        const float* src = incoming + ((size_t)t * B_SZ + b) * E_DIM + 2 * k2;
        g_INC2T[(size_t)t * ((E_DIM / 2) * B_SZ) + idx] = make_float2(src[0], src[1]);
    }
    {
        int g = t * 256 + tid;           // 128*256 = 32768 = (H/2)*B
        int k2 = g >> 6;
        g_H2T[0][g] = make_float2(h_init[2 * k2], h_init[2 * k2 + 1]);
    }
    if (t == 0 && tid == 0) { g_count = 0u; g_release = 0u; }
}

// ---------------- gates chunk prefetch (cp.async) ----------------
__device__ __forceinline__ void prefetch_chunk(
    char* smem, int buf, int chunkIdx, int t,
    const float* __restrict__ wih, const float* __restrict__ whh,
    const float2* __restrict__ hcur, int jbase, int half, int tid)
{
    int part = chunkIdx >> 3, c = chunkIdx & 7;
    const float* W = part ? whh : wih;
    float* wd = (float*)(smem + OFF_W) + buf * 6144;
#pragma unroll
    for (int i = 0; i < 3; i++) {
        int idx = tid + i * NTHR;        // 0..1535
        int row = idx >> 5;              // 0..47
        int seg = idx & 31;
        int g = row >> 4, r = row & 15;
        const float* gsrc = W + ((size_t)(g * H_DIM + jbase + r)) * 1024 + c * 128 + seg * 4;
        cpa16(wd + (g * 16 + r) * 128 + seg * 4, gsrc);
    }
    const float2* src;
    if (part)          src = hcur + c * 64 * B_SZ;
    else if (c < 4)    src = g_INC2T + ((size_t)t * (E_DIM / 2) + c * 64) * B_SZ;
    else               src = g_CTX2T + (size_t)(c - 4) * 64 * B_SZ;
    float2* xd = (float2*)(smem + OFF_X) + buf * 2048;
#pragma unroll
    for (int i = 0; i < 2; i++) {
        int idx = tid + i * NTHR;        // 0..1023
        int k2 = idx >> 4, seg = idx & 15;
        cpa16(xd + k2 * 32 + seg * 2, src + k2 * 64 + half * 32 + seg * 2);
    }
}

// ---------------- persistent recurrent kernel ----------------
__global__ void __launch_bounds__(NTHR, 1) gru_kernel(
    const float* __restrict__ post,
    const float* __restrict__ wih,
    const float* __restrict__ whh,
    const float* __restrict__ bih,
    const float* __restrict__ bhh,
    const float* __restrict__ wq,
    const float* __restrict__ bq,
    const int* __restrict__ length,
    const int* __restrict__ post_length,
    float* __restrict__ out,
    int write_last)
{
    extern __shared__ __align__(16) char smem[];
    float* s_q    = (float*)(smem + OFF_Q);
    float* s_sc   = (float*)(smem + OFF_SC);
    u64*   s_e2   = (u64*)(smem + OFF_E2);
    float* s_stat = (float*)(smem + OFF_STAT);
    float* s_part = (float*)(smem + OFF_PART);   // [16][4][32]

    const int tid = threadIdx.x;
    const int bx = blockIdx.x;
    const int wid = tid >> 5;
    const int lane = tid & 31;

    // gates-phase constants
    const int g_half  = bx & 1;
    const int g_jbase = (bx >> 1) * 16;
    const int g_j     = g_jbase + wid;           // one j per warp
    const int g_b     = g_half * 32 + lane;
    const int g_len   = length[g_b];

    // Q-phase constants: warp computes 4 d's (d0..d0+3) for one half, one K-eighth
    const int q_half = wid >> 3;
    const int q_kq   = wid & 7;
    const int q_b    = q_half * 32 + lane;
    const int q_d0   = bx * 4;

    unsigned int ep = 0;

    for (int t = 0; t < S_LEN; t++) {
        const float2* hcur = g_H2T[t & 1];
        float2* hnext      = g_H2T[(t & 1) ^ 1];

        // ================= Phase 1: Q = h @ wq^T + bq =================
        {
            const u64* hsrc = (const u64*)hcur;
            u64 a[4] = {0ull, 0ull, 0ull, 0ull};
#pragma unroll 4
            for (int k4r = 0; k4r < 32; k4r++) {
                int k4 = q_kq * 32 + k4r;
                u64 xa = hsrc[(2 * k4) * B_SZ + q_b];
                u64 xb = hsrc[(2 * k4 + 1) * B_SZ + q_b];
#pragma unroll
                for (int dd = 0; dd < 4; dd++) {
                    ulonglong2 w = *(const ulonglong2*)(wq + (size_t)(q_d0 + dd) * H_DIM + k4 * 4);
                    ffma2(a[dd], w.x, xa);
                    ffma2(a[dd], w.y, xb);
                }
            }
#pragma unroll
            for (int dd = 0; dd < 4; dd++)
                s_part[(wid * 4 + dd) * 32 + lane] = sum2(a[dd]);
            __syncthreads();
            if (tid < 256) {
                int dd = tid >> 6;       // 0..3
                int b  = tid & 63;       // == half*32+lane
                int half2 = b >> 5, ln = b & 31;
                float s = 0.f;
#pragma unroll
                for (int kq = 0; kq < 8; kq++)
                    s += s_part[((half2 * 8 + kq) * 4 + dd) * 32 + ln];
                int d = q_d0 + dd;
                g_Qrow[(size_t)b * PD + d] = s + bq[d];
            }
        }
        ep++; gsync(ep);

        // ================= Phase 2: attention (blocks 0..63 = batch) =================
        if (bx < B_SZ) {
            const int b = bx;
            s_q[tid] = g_Qrow[(size_t)b * PD + tid];
            __syncthreads();

            int pl = post_length[b];
            const ulonglong2* qq = (const ulonglong2*)s_q;
            for (int p = wid; p < PL; p += 16) {
                const ulonglong2* pp = (const ulonglong2*)(post + ((size_t)p * B_SZ + b) * PD);
                u64 a0 = 0ull, a1 = 0ull;
#pragma unroll 2
                for (int i = lane; i < PD / 4; i += 32) {
                    ulonglong2 pv = pp[i];
                    ulonglong2 qv = qq[i];
                    ffma2(a0, pv.x, qv.x);
                    ffma2(a1, pv.y, qv.y);
                }
                float s = sum2(a0) + sum2(a1);
#pragma unroll
                for (int o = 16; o > 0; o >>= 1)
                    s += __shfl_xor_sync(0xffffffffu, s, o);
                if (lane == 0) s_sc[p] = (p < pl) ? s : -1e30f;
            }
            __syncthreads();

            if (tid < 32) {
                float m = -1e30f;
                for (int p = tid; p < PL; p += 32) m = fmaxf(m, s_sc[p]);
#pragma unroll
                for (int o = 16; o > 0; o >>= 1)
                    m = fmaxf(m, __shfl_xor_sync(0xffffffffu, m, o));
                if (tid == 0) s_stat[0] = m;
            }
            __syncthreads();
            if (tid < PL) {
                float e = __expf(s_sc[tid] - s_stat[0]);
                s_sc[tid] = e;
                float2 ee = make_float2(e, e);
                s_e2[tid] = *(u64*)&ee;
            }
            __syncthreads();
            if (tid < 32) {
                float s = 0.f;
                for (int p = tid; p < PL; p += 32) s += s_sc[p];
#pragma unroll
                for (int o = 16; o > 0; o >>= 1)
                    s += __shfl_xor_sync(0xffffffffu, s, o);
                if (tid == 0) s_stat[1] = 1.f / s;
            }
            __syncthreads();

            if (tid < 256) {   // context: thread = d-pair, packed FFMA2, transposed write
                const u64* pb = (const u64*)post + (size_t)b * (PD / 2) + tid;
                u64 c0 = 0ull, c1 = 0ull;
#pragma unroll 4
                for (int p = 0; p < PL; p += 2) {
                    ffma2(c0, s_e2[p],     pb[(size_t)p * (B_SZ * PD / 2)]);
                    ffma2(c1, s_e2[p + 1], pb[(size_t)(p + 1) * (B_SZ * PD / 2)]);
                }
                u64 c2;
                asm("add.rn.f32x2 %0, %1, %2;" : "=l"(c2) : "l"(c0), "l"(c1));
                float inv = s_stat[1];
                float lo = __int_as_float((unsigned)(c2 & 0xffffffffULL));
                float hi = __int_as_float((unsigned)(c2 >> 32));
                g_CTX2T[tid * B_SZ + b] = make_float2(lo * inv, hi * inv);
            }
        }
        ep++; gsync(ep);

        // ================= Phase 3: GRU gates (cp.async double-buffered) =================
        {
            u64 acc[2][3];
#pragma unroll
            for (int p = 0; p < 2; p++)
#pragma unroll
                for (int g = 0; g < 3; g++) acc[p][g] = 0ull;

            int buf = 0;
            prefetch_chunk(smem, 0, 0, t, wih, whh, hcur, g_jbase, g_half, tid);
            asm volatile("cp.async.commit_group;" ::: "memory");

            for (int ch = 0; ch < 16; ch++) {
                if (ch < 15) {
                    prefetch_chunk(smem, buf ^ 1, ch + 1, t, wih, whh, hcur,
                                   g_jbase, g_half, tid);
                    asm volatile("cp.async.commit_group;" ::: "memory");
                    asm volatile("cp.async.wait_group 1;" ::: "memory");
                } else {
                    asm volatile("cp.async.wait_group 0;" ::: "memory");
                }
                __syncthreads();

                int part = ch >> 3;
                const float* wb = (const float*)(smem + OFF_W) + buf * 6144;
                const u64* xb = (const u64*)((const float2*)(smem + OFF_X) + buf * 2048);
#pragma unroll 4
                for (int k4 = 0; k4 < 32; k4++) {
                    u64 xa = xb[(2 * k4) * 32 + lane];
                    u64 xc = xb[(2 * k4 + 1) * 32 + lane];
#pragma unroll
                    for (int g = 0; g < 3; g++) {
                        ulonglong2 w = *(const ulonglong2*)(wb + (g * 16 + wid) * 128 + k4 * 4);
                        ffma2(acc[part][g], w.x, xa);
                        ffma2(acc[part][g], w.y, xc);
                    }
                }
                __syncthreads();
                buf ^= 1;
            }

            // combine + activations + writes
            float2 hp2 = hcur[(g_j >> 1) * B_SZ + g_b];
            float hp = (g_j & 1) ? hp2.y : hp2.x;
            float ir  = sum2(acc[0][0]) + bih[g_j];
            float iz  = sum2(acc[0][1]) + bih[H_DIM + g_j];
            float inn = sum2(acc[0][2]) + bih[2 * H_DIM + g_j];
            float hr  = sum2(acc[1][0]) + bhh[g_j];
            float hz  = sum2(acc[1][1]) + bhh[H_DIM + g_j];
            float hnn = sum2(acc[1][2]) + bhh[2 * H_DIM + g_j];
            float r = 1.f / (1.f + __expf(-(ir + hr)));
            float z = 1.f / (1.f + __expf(-(iz + hz)));
            float n = tanhf(inn + r * hnn);
            float hn = (1.f - z) * n + z * hp;
            if (g_len <= t) hn = 0.f;

            ((float*)hnext)[((g_j >> 1) * B_SZ + g_b) * 2 + (g_j & 1)] = hn;
            out[((size_t)t * B_SZ + g_b) * H_DIM + g_j] = hn;
            if (write_last && t == S_LEN - 1) {
                out[(size_t)S_LEN * B_SZ * H_DIM + (size_t)g_b * H_DIM + g_j] = hn;
            }
        }
        ep++; gsync(ep);
    }
}

// ---------------- launch ----------------
extern "C" void kernel_launch(void* const* d_in, const int* in_sizes, int n_in,
                              void* d_out, int out_size) {
    const float* incoming    = (const float*)d_in[0];
    const float* post        = (const float*)d_in[1];
    const float* h_init      = (const float*)d_in[2];
    const float* wih         = (const float*)d_in[3];
    const float* whh         = (const float*)d_in[4];
    const float* bih         = (const float*)d_in[5];
    const float* bhh         = (const float*)d_in[6];
    const float* wq          = (const float*)d_in[7];
    const float* bq          = (const float*)d_in[8];
    const int*   length      = (const int*)d_in[9];
    const int*   post_length = (const int*)d_in[10];
    float* out = (float*)d_out;

    int write_last = (out_size >= S_LEN * B_SZ * H_DIM + B_SZ * H_DIM) ? 1 : 0;

    static int smem_set = 0;
    if (!smem_set) {
        cudaFuncSetAttribute(gru_kernel, cudaFuncAttributeMaxDynamicSharedMemorySize,
                             SMEM_SZ);
        smem_set = 1;
    }

    pre_kernel<<<S_LEN, 256>>>(incoming, h_init);
    gru_kernel<<<NBLK, NTHR, SMEM_SZ>>>(post, wih, whh, bih, bhh, wq, bq,
                                        length, post_length, out, write_last);
}

// round 7
// speedup vs baseline: 1.5584x; 1.0213x over previous
#include <cuda_runtime.h>

#define S_LEN 128
#define B_SZ  64
#define E_DIM 512
#define PL    160
#define PD    512
#define H_DIM 1024

#define NBLK 128
#define NTHR 512

typedef unsigned long long u64;

// ---------------- persistent scratch (device globals) ----------------
__device__ __align__(16) float g_H[2][B_SZ * H_DIM];   // [buf][b][k]
__device__ __align__(16) float g_CTX[B_SZ * PD];       // [b][d]
__device__ __align__(16) float g_Q[B_SZ * PD];         // [b][d]
__device__ __align__(16) float g_SC[B_SZ * PL];        // [b][p]
__device__ unsigned int g_count;
__device__ unsigned int g_release;

// ---------------- smem layout (dynamic), W/x rows padded to 132 floats ----------------
#define WROWS   48                    // 3 gates x 16 j
#define WBUFF   (WROWS * 132)         // floats per W buffer = 6336
#define XBUFF   (32 * 132)            // floats per x buffer = 4224
#define OFF_W   0                     // float [2][6336]  = 50688 B
#define OFF_X   50688                 // float [2][4224]  = 33792 B
#define OFF_Q   84480                 // float [512]
#define OFF_SC  86528                 // float [160]
#define OFF_E2  87168                 // u64   [160]
#define OFF_ST  88448                 // float [2]
#define SMEM_SZ 88576

// ---------------- packed f32x2 helpers ----------------
__device__ __forceinline__ void ffma2(u64& d, u64 a, u64 b) {
    asm("fma.rn.f32x2 %0, %1, %2, %0;" : "+l"(d) : "l"(a), "l"(b));
}
__device__ __forceinline__ float sum2(u64 v) {
    float lo = __int_as_float((unsigned)(v & 0xffffffffULL));
    float hi = __int_as_float((unsigned)(v >> 32));
    return lo + hi;
}

// ---------------- cp.async ----------------
__device__ __forceinline__ void cpa16(void* s, const void* g) {
    unsigned saddr = (unsigned)__cvta_generic_to_shared(s);
    asm volatile("cp.async.ca.shared.global [%0], [%1], 16;" :: "r"(saddr), "l"(g));
}

// ---------------- grid-wide epoch barrier ----------------
__device__ __forceinline__ void gsync(unsigned int epoch) {
    __syncthreads();
    if (threadIdx.x == 0) {
        __threadfence();
        unsigned int arrived = atomicAdd(&g_count, 1u) + 1u;
        if (arrived == (unsigned)NBLK * epoch) {
            atomicExch(&g_release, epoch);
        } else {
            while (*(volatile unsigned int*)&g_release < epoch) {
                __nanosleep(40);
            }
        }
        __threadfence();
    }
    __syncthreads();
}

// ---------------- pre-pass: h0 broadcast, barrier reset ----------------
__global__ void pre_kernel(const float* __restrict__ h_init) {
    int b = blockIdx.x;
    for (int k = threadIdx.x; k < H_DIM; k += 256)
        g_H[0][b * H_DIM + k] = h_init[k];
    if (b == 0 && threadIdx.x == 0) { g_count = 0u; g_release = 0u; }
}

// ---------------- gates chunk prefetch ----------------
__device__ __forceinline__ void prefetch_chunk(
    char* smem, int buf, int ch, int t,
    const float* __restrict__ wih, const float* __restrict__ whh,
    const float* __restrict__ hcur, const float* __restrict__ incoming,
    int jbase, int half, int tid)
{
    int part = ch >> 3, c = ch & 7;
    const float* W = part ? whh : wih;
    float* wd = (float*)(smem + OFF_W) + buf * WBUFF;
#pragma unroll
    for (int i = 0; i < 3; i++) {
        int idx = tid + i * NTHR;        // 0..1535
        int row = idx >> 5;              // 0..47
        int seg = idx & 31;
        int g = row >> 4, r = row & 15;
        const float* src = W + ((size_t)(g * H_DIM + jbase + r)) * 1024 + c * 128 + seg * 4;
        cpa16(wd + row * 132 + seg * 4, src);
    }
    float* xd = (float*)(smem + OFF_X) + buf * XBUFF;
#pragma unroll
    for (int i = 0; i < 2; i++) {
        int idx = tid + i * NTHR;        // 0..1023
        int b = idx >> 5;                // local b 0..31
        int seg = idx & 31;
        int gb = half * 32 + b;
        const float* src;
        if (part)       src = hcur + (size_t)gb * H_DIM + c * 128;
        else if (c < 4) src = incoming + ((size_t)t * B_SZ + gb) * E_DIM + c * 128;
        else            src = g_CTX + (size_t)gb * PD + (c - 4) * 128;
        cpa16(xd + b * 132 + seg * 4, src + seg * 4);
    }
}

// ---------------- persistent recurrent kernel ----------------
__global__ void __launch_bounds__(NTHR, 1) gru_kernel(
    const float* __restrict__ incoming,
    const float* __restrict__ post,
    const float* __restrict__ wih,
    const float* __restrict__ whh,
    const float* __restrict__ bih,
    const float* __restrict__ bhh,
    const float* __restrict__ wq,
    const float* __restrict__ bq,
    const int* __restrict__ length,
    const int* __restrict__ post_length,
    float* __restrict__ out,
    int write_last)
{
    extern __shared__ __align__(16) char smem[];
    float* s_q  = (float*)(smem + OFF_Q);
    float* s_sc = (float*)(smem + OFF_SC);
    u64*   s_e2 = (u64*)(smem + OFF_E2);
    float* s_st = (float*)(smem + OFF_ST);

    const int tid = threadIdx.x;
    const int bx = blockIdx.x;
    const int wid = tid >> 5;
    const int lane = tid & 31;

    // gates constants: warp tile 4j x 8b
    const int g_half  = bx & 1;
    const int g_jbase = (bx >> 1) * 16;
    const int jt = wid >> 2, bt = wid & 3;
    const int j_sub = lane >> 3, bl = lane & 7;
    const int g_lb  = bt * 8 + bl;                 // local b 0..31
    const int g_b   = g_half * 32 + g_lb;
    const int g_j   = g_jbase + jt * 4 + j_sub;
    const int g_len = length[g_b];

    // attention constants
    const int a_b  = bx >> 1;
    const int a_hf = bx & 1;

    unsigned int ep = 0;

    for (int t = 0; t < S_LEN; t++) {
        const float* hcur = g_H[t & 1];
        float* hnext      = g_H[(t & 1) ^ 1];

        // ================= Phase 1: Q = h @ wq^T + bq (register-only) =================
        {
            int d0 = bx * 4;
#pragma unroll 1
            for (int bp = 0; bp < 4; bp++) {
                int b = wid * 4 + bp;
                const ulonglong2* hrow = (const ulonglong2*)(hcur + (size_t)b * H_DIM);
                ulonglong2 hx[8];
#pragma unroll
                for (int s = 0; s < 8; s++) hx[s] = hrow[s * 32 + lane];
#pragma unroll
                for (int dd = 0; dd < 4; dd++) {
                    const ulonglong2* wrow = (const ulonglong2*)(wq + (size_t)(d0 + dd) * H_DIM);
                    u64 a0 = 0ull, a1 = 0ull;
#pragma unroll
                    for (int s = 0; s < 8; s++) {
                        ulonglong2 wv = wrow[s * 32 + lane];
                        ffma2(a0, wv.x, hx[s].x);
                        ffma2(a1, wv.y, hx[s].y);
                    }
                    float sres = sum2(a0) + sum2(a1);
#pragma unroll
                    for (int o = 16; o > 0; o >>= 1)
                        sres += __shfl_xor_sync(0xffffffffu, sres, o);
                    if (lane == 0)
                        g_Q[(size_t)b * PD + d0 + dd] = sres + bq[d0 + dd];
                }
            }
        }
        ep++; gsync(ep);

        // ================= Phase 2a: scores (all 128 blocks; p split) =================
        {
            const int b = a_b;
            s_q[tid] = g_Q[(size_t)b * PD + tid];
            __syncthreads();
            int pl = post_length[b];
            const ulonglong2* qq = (const ulonglong2*)s_q;
#pragma unroll 1
            for (int i = 0; i < 5; i++) {
                int p = a_hf * 80 + wid * 5 + i;
                const ulonglong2* pp = (const ulonglong2*)(post + ((size_t)p * B_SZ + b) * PD);
                u64 a0 = 0ull, a1 = 0ull;
#pragma unroll
                for (int s = lane; s < PD / 4; s += 32) {
                    ulonglong2 pv = pp[s];
                    ulonglong2 qv = qq[s];
                    ffma2(a0, pv.x, qv.x);
                    ffma2(a1, pv.y, qv.y);
                }
                float sres = sum2(a0) + sum2(a1);
#pragma unroll
                for (int o = 16; o > 0; o >>= 1)
                    sres += __shfl_xor_sync(0xffffffffu, sres, o);
                if (lane == 0)
                    g_SC[b * PL + p] = (p < pl) ? sres : -1e30f;
            }
        }
        ep++; gsync(ep);

        // ================= Phase 2b: softmax + context (d split) =================
        {
            const int b = a_b;
            if (tid < PL) s_sc[tid] = g_SC[b * PL + tid];
            __syncthreads();
            if (tid < 32) {
                float m = -1e30f;
                for (int p = tid; p < PL; p += 32) m = fmaxf(m, s_sc[p]);
#pragma unroll
                for (int o = 16; o > 0; o >>= 1)
                    m = fmaxf(m, __shfl_xor_sync(0xffffffffu, m, o));
                if (tid == 0) s_st[0] = m;
            }
            __syncthreads();
            if (tid < PL) {
                float e = __expf(s_sc[tid] - s_st[0]);
                s_sc[tid] = e;
                float2 ee = make_float2(e, e);
                s_e2[tid] = *(u64*)&ee;
            }
            __syncthreads();
            if (tid < 32) {
                float s = 0.f;
                for (int p = tid; p < PL; p += 32) s += s_sc[p];
#pragma unroll
                for (int o = 16; o > 0; o >>= 1)
                    s += __shfl_xor_sync(0xffffffffu, s, o);
                if (tid == 0) s_st[1] = 1.f / s;
            }
            __syncthreads();
            if (tid < 128) {   // 128 d-pairs of this block's half
                int dp = a_hf * 128 + tid;
                const u64* pb = (const u64*)post + (size_t)b * (PD / 2) + dp;
                u64 c0 = 0ull, c1 = 0ull;
#pragma unroll 4
                for (int p = 0; p < PL; p += 2) {
                    ffma2(c0, s_e2[p],     pb[(size_t)p * (B_SZ * PD / 2)]);
                    ffma2(c1, s_e2[p + 1], pb[(size_t)(p + 1) * (B_SZ * PD / 2)]);
                }
                u64 c2;
                asm("add.rn.f32x2 %0, %1, %2;" : "=l"(c2) : "l"(c0), "l"(c1));
                float inv = s_st[1];
                float lo = __int_as_float((unsigned)(c2 & 0xffffffffULL)) * inv;
                float hi = __int_as_float((unsigned)(c2 >> 32)) * inv;
                *(float2*)&g_CTX[(size_t)b * PD + 2 * dp] = make_float2(lo, hi);
            }
        }
        // hoist chunk-0 prefetch (incoming part — no ctx dependency)
        prefetch_chunk(smem, 0, 0, t, wih, whh, hcur, incoming, g_jbase, g_half, tid);
        asm volatile("cp.async.commit_group;" ::: "memory");
        ep++; gsync(ep);

        // ================= Phase 3: GRU gates (4j x 8b register tiles) =================
        {
            u64 acc[2][3];
#pragma unroll
            for (int p = 0; p < 2; p++)
#pragma unroll
                for (int g = 0; g < 3; g++) acc[p][g] = 0ull;

            int buf = 0;
            for (int ch = 0; ch < 16; ch++) {
                if (ch < 15) {
                    prefetch_chunk(smem, buf ^ 1, ch + 1, t, wih, whh, hcur,
                                   incoming, g_jbase, g_half, tid);
                    asm volatile("cp.async.commit_group;" ::: "memory");
                    asm volatile("cp.async.wait_group 1;" ::: "memory");
                } else {
                    asm volatile("cp.async.wait_group 0;" ::: "memory");
                }
                __syncthreads();

                int part = ch >> 3;
                const float* wbase = (const float*)(smem + OFF_W) + buf * WBUFF;
                const float* xbase = (const float*)(smem + OFF_X) + buf * XBUFF + g_lb * 132;
                const int wrow = jt * 4 + j_sub;
#pragma unroll
                for (int k16 = 0; k16 < 8; k16++) {
                    const ulonglong2* xp = (const ulonglong2*)(xbase + k16 * 16);
                    ulonglong2 xA = xp[0], xB = xp[1], xC = xp[2], xD = xp[3];
#pragma unroll
                    for (int g = 0; g < 3; g++) {
                        const ulonglong2* wp = (const ulonglong2*)
                            (wbase + (g * 16 + wrow) * 132 + k16 * 16);
                        ulonglong2 wA = wp[0], wB = wp[1], wC = wp[2], wD = wp[3];
                        ffma2(acc[part][g], wA.x, xA.x);
                        ffma2(acc[part][g], wA.y, xA.y);
                        ffma2(acc[part][g], wB.x, xB.x);
                        ffma2(acc[part][g], wB.y, xB.y);
                        ffma2(acc[part][g], wC.x, xC.x);
                        ffma2(acc[part][g], wC.y, xC.y);
                        ffma2(acc[part][g], wD.x, xD.x);
                        ffma2(acc[part][g], wD.y, xD.y);
                    }
                }
                __syncthreads();
                buf ^= 1;
            }

            // epilogue
            float hp  = hcur[(size_t)g_b * H_DIM + g_j];
            float ir  = sum2(acc[0][0]) + bih[g_j];
            float iz  = sum2(acc[0][1]) + bih[H_DIM + g_j];
            float inn = sum2(acc[0][2]) + bih[2 * H_DIM + g_j];
            float hr  = sum2(acc[1][0]) + bhh[g_j];
            float hz  = sum2(acc[1][1]) + bhh[H_DIM + g_j];
            float hnn = sum2(acc[1][2]) + bhh[2 * H_DIM + g_j];
            float r = 1.f / (1.f + __expf(-(ir + hr)));
            float z = 1.f / (1.f + __expf(-(iz + hz)));
            float n = tanhf(inn + r * hnn);
            float hn = (1.f - z) * n + z * hp;
            if (g_len <= t) hn = 0.f;

            hnext[(size_t)g_b * H_DIM + g_j] = hn;
            out[((size_t)t * B_SZ + g_b) * H_DIM + g_j] = hn;
            if (write_last && t == S_LEN - 1) {
                out[(size_t)S_LEN * B_SZ * H_DIM + (size_t)g_b * H_DIM + g_j] = hn;
            }
        }
        ep++; gsync(ep);
    }
}

// ---------------- launch ----------------
extern "C" void kernel_launch(void* const* d_in, const int* in_sizes, int n_in,
                              void* d_out, int out_size) {
    const float* incoming    = (const float*)d_in[0];
    const float* post        = (const float*)d_in[1];
    const float* h_init      = (const float*)d_in[2];
    const float* wih         = (const float*)d_in[3];
    const float* whh         = (const float*)d_in[4];
    const float* bih         = (const float*)d_in[5];
    const float* bhh         = (const float*)d_in[6];
    const float* wq          = (const float*)d_in[7];
    const float* bq          = (const float*)d_in[8];
    const int*   length      = (const int*)d_in[9];
    const int*   post_length = (const int*)d_in[10];
    float* out = (float*)d_out;

    int write_last = (out_size >= S_LEN * B_SZ * H_DIM + B_SZ * H_DIM) ? 1 : 0;

    cudaFuncSetAttribute(gru_kernel, cudaFuncAttributeMaxDynamicSharedMemorySize,
                         SMEM_SZ);

    pre_kernel<<<B_SZ, 256>>>(h_init);
    gru_kernel<<<NBLK, NTHR, SMEM_SZ>>>(incoming, post, wih, whh, bih, bhh,
                                        wq, bq, length, post_length, out,
                                        write_last);
}

// round 11
// speedup vs baseline: 1.6670x; 1.0697x over previous
#include <cuda_runtime.h>

#define S_LEN 128
#define B_SZ  64
#define E_DIM 512
#define PL    160
#define PD    512
#define H_DIM 1024

#define NBLK 128
#define NTHR 512

typedef unsigned long long u64;

// ---------------- persistent scratch (device globals) ----------------
__device__ __align__(16) float g_H[2][B_SZ * H_DIM];   // [buf][b][k]
__device__ __align__(16) float g_CTX[B_SZ * PD];       // [b][d]
__device__ __align__(16) float g_Q[B_SZ * PD];         // [b][d]
__device__ __align__(16) float g_SC[B_SZ * PL];        // [b][p]
__device__ unsigned int g_count;
__device__ unsigned int g_release;

// ---------------- smem layout (bytes); W/x rows padded to 260 floats ----------------
#define WPAD    260
#define WBUF_F  (48 * WPAD)            // 12480 floats / buffer
#define XBUF_F  (32 * WPAD)            // 8320 floats / buffer
#define OFF_W   0                      // 2 * 49920 = 99840
#define OFF_X   99840                  // 2 * 33280 = 66560
#define OFF_WQ  166400                 // 4096 floats = 16384
#define OFF_Q   182784                 // 512 floats
#define OFF_SC  184832                 // 160 floats
#define OFF_E2  185472                 // 160 u64
#define OFF_ST  186752                 // 2 floats
#define OFF_MB  186768                 // 2 mbarriers (8B each)
#define SMEM_SZ 186880

#define CHUNK_TX (80u * 1024u)         // 48 W rows + 32 x rows, 1KB each

// ---------------- packed f32x2 helpers ----------------
__device__ __forceinline__ void ffma2(u64& d, u64 a, u64 b) {
    asm("fma.rn.f32x2 %0, %1, %2, %0;" : "+l"(d) : "l"(a), "l"(b));
}
__device__ __forceinline__ float sum2(u64 v) {
    float lo = __int_as_float((unsigned)(v & 0xffffffffULL));
    float hi = __int_as_float((unsigned)(v >> 32));
    return lo + hi;
}

// ---------------- bulk TMA + mbarrier ----------------
__device__ __forceinline__ void bulk1k(void* sdst, const void* gsrc, unsigned mbar) {
    unsigned sd = (unsigned)__cvta_generic_to_shared(sdst);
    asm volatile(
        "cp.async.bulk.shared::cluster.global.mbarrier::complete_tx::bytes "
        "[%0], [%1], %2, [%3];"
        :: "r"(sd), "l"(gsrc), "r"(1024), "r"(mbar) : "memory");
}
__device__ __forceinline__ void mbar_init(unsigned mbar, unsigned cnt) {
    asm volatile("mbarrier.init.shared.b64 [%0], %1;" :: "r"(mbar), "r"(cnt) : "memory");
}
__device__ __forceinline__ void mbar_expect(unsigned mbar, unsigned tx) {
    asm volatile("mbarrier.arrive.expect_tx.shared.b64 _, [%0], %1;"
                 :: "r"(mbar), "r"(tx) : "memory");
}
__device__ __forceinline__ void mbar_wait(unsigned mbar, unsigned parity) {
    asm volatile(
        "{\n\t"
        ".reg .pred P1;\n\t"
        "WAIT_LOOP_%=:\n\t"
        "mbarrier.try_wait.parity.acquire.cta.shared::cta.b64 P1, [%0], %1, 0x989680;\n\t"
        "@P1 bra.uni WAIT_DONE_%=;\n\t"
        "bra.uni WAIT_LOOP_%=;\n\t"
        "WAIT_DONE_%=:\n\t"
        "}"
        :: "r"(mbar), "r"(parity) : "memory");
}

// ---------------- grid-wide epoch barrier ----------------
__device__ __forceinline__ void gsync(unsigned int epoch) {
    __syncthreads();
    if (threadIdx.x == 0) {
        __threadfence();
        unsigned int arrived = atomicAdd(&g_count, 1u) + 1u;
        if (arrived == (unsigned)NBLK * epoch) {
            atomicExch(&g_release, epoch);
        } else {
            while (*(volatile unsigned int*)&g_release < epoch) {
                __nanosleep(40);
            }
        }
        __threadfence();
    }
    __syncthreads();
}

// ---------------- pre-pass: h0 broadcast, barrier reset ----------------
__global__ void pre_kernel(const float* __restrict__ h_init) {
    int b = blockIdx.x;
    for (int k = threadIdx.x; k < H_DIM; k += 256)
        g_H[0][b * H_DIM + k] = h_init[k];
    if (b == 0 && threadIdx.x == 0) { g_count = 0u; g_release = 0u; }
}

// ---------------- gates chunk prefetch (bulk TMA, warp 0 only) ----------------
// chunk map: ch 0-3 = h (whh, kc=ch); ch 4-5 = xt (wih, kc=ch-4); ch 6-7 = ctx (wih, kc=ch-4)
__device__ __forceinline__ void prefetch_bulk(
    char* smem, unsigned smem_u32, int buf, int ch, int t,
    const float* __restrict__ wih, const float* __restrict__ whh,
    const float* __restrict__ hcur, const float* __restrict__ incoming,
    int jbase, int half, int wid, int lane)
{
    if (wid != 0) return;
    unsigned mbar = smem_u32 + OFF_MB + buf * 8;
    if (lane == 0) mbar_expect(mbar, CHUNK_TX);
    __syncwarp();

    int part = (ch < 4) ? 1 : 0;
    int kc = part ? ch : (ch - 4);
    const float* W = part ? whh : wih;
    float* wd = (float*)(smem + OFF_W) + buf * WBUF_F;
    float* xd = (float*)(smem + OFF_X) + buf * XBUF_F;

#pragma unroll
    for (int i = 0; i < 3; i++) {
        int row = lane + 32 * i;        // 0..95, use < 80
        if (row < 48) {
            int g = row >> 4, r = row & 15;
            const float* src = W + ((size_t)(g * H_DIM + jbase + r)) * 1024 + kc * 256;
            bulk1k(wd + row * WPAD, src, mbar);
        } else if (row < 80) {
            int b = row - 48;
            int gb = half * 32 + b;
            const float* src;
            if (part)        src = hcur + (size_t)gb * H_DIM + kc * 256;
            else if (kc < 2) src = incoming + ((size_t)t * B_SZ + gb) * E_DIM + kc * 256;
            else             src = g_CTX + (size_t)gb * PD + (kc - 2) * 256;
            bulk1k(xd + b * WPAD, src, mbar);
        }
    }
}

// ---------------- persistent recurrent kernel ----------------
__global__ void __launch_bounds__(NTHR, 1) gru_kernel(
    const float* __restrict__ incoming,
    const float* __restrict__ post,
    const float* __restrict__ wih,
    const float* __restrict__ whh,
    const float* __restrict__ bih,
    const float* __restrict__ bhh,
    const float* __restrict__ wq,
    const float* __restrict__ bq,
    const int* __restrict__ length,
    const int* __restrict__ post_length,
    float* __restrict__ out,
    int write_last)
{
    extern __shared__ __align__(16) char smem[];
    float* s_wq = (float*)(smem + OFF_WQ);
    float* s_q  = (float*)(smem + OFF_Q);
    float* s_sc = (float*)(smem + OFF_SC);
    u64*   s_e2 = (u64*)(smem + OFF_E2);
    float* s_st = (float*)(smem + OFF_ST);
    unsigned smem_u32 = (unsigned)__cvta_generic_to_shared(smem);

    const int tid = threadIdx.x;
    const int bx = blockIdx.x;
    const int wid = tid >> 5;
    const int lane = tid & 31;

    // gates constants: warp tile 4j x 8b
    const int g_half  = bx & 1;
    const int g_jbase = (bx >> 1) * 16;
    const int jt = wid >> 2, bt = wid & 3;
    const int j_sub = lane >> 3, bl = lane & 7;
    const int g_lb  = bt * 8 + bl;
    const int g_b   = g_half * 32 + g_lb;
    const int g_j   = g_jbase + jt * 4 + j_sub;
    const int g_len = length[g_b];

    // attention constants
    const int a_b  = bx >> 1;
    const int a_hf = bx & 1;

    // one-time: init mbarriers + cache wq rows (t-invariant)
    if (tid == 0) {
        mbar_init(smem_u32 + OFF_MB + 0, 1);
        mbar_init(smem_u32 + OFF_MB + 8, 1);
        asm volatile("fence.proxy.async.shared::cta;" ::: "memory");
    }
    {
        const float4* src = (const float4*)(wq + (size_t)bx * 4 * H_DIM);
        float4* dst = (float4*)s_wq;
        for (int i = tid; i < 1024; i += NTHR) dst[i] = src[i];
    }
    __syncthreads();

    unsigned int ep = 0;

    for (int t = 0; t < S_LEN; t++) {
        const float* hcur = g_H[t & 1];
        float* hnext      = g_H[(t & 1) ^ 1];

        // kick off gates chunks 0,1 (h-part; ready now) — overlap Q+attention
        prefetch_bulk(smem, smem_u32, 0, 0, t, wih, whh, hcur, incoming,
                      g_jbase, g_half, wid, lane);
        prefetch_bulk(smem, smem_u32, 1, 1, t, wih, whh, hcur, incoming,
                      g_jbase, g_half, wid, lane);

        // ================= Phase 1: Q = h @ wq^T + bq (wq from smem) =================
        {
            int d0 = bx * 4;
#pragma unroll 1
            for (int bp = 0; bp < 4; bp++) {
                int b = wid * 4 + bp;
                const ulonglong2* hrow = (const ulonglong2*)(hcur + (size_t)b * H_DIM);
                ulonglong2 hx[8];
#pragma unroll
                for (int s = 0; s < 8; s++) hx[s] = hrow[s * 32 + lane];
#pragma unroll
                for (int dd = 0; dd < 4; dd++) {
                    const ulonglong2* wrow = (const ulonglong2*)(s_wq + dd * H_DIM);
                    u64 a0 = 0ull, a1 = 0ull;
#pragma unroll
                    for (int s = 0; s < 8; s++) {
                        ulonglong2 wv = wrow[s * 32 + lane];
                        ffma2(a0, wv.x, hx[s].x);
                        ffma2(a1, wv.y, hx[s].y);
                    }
                    float sres = sum2(a0) + sum2(a1);
#pragma unroll
                    for (int o = 16; o > 0; o >>= 1)
                        sres += __shfl_xor_sync(0xffffffffu, sres, o);
                    if (lane == 0)
                        g_Q[(size_t)b * PD + d0 + dd] = sres + bq[d0 + dd];
                }
            }
        }
        ep++; gsync(ep);

        // ================= Phase 2a: scores (p split across block halves) =================
        {
            const int b = a_b;
            s_q[tid] = g_Q[(size_t)b * PD + tid];
            __syncthreads();
            int pl = post_length[b];
            const ulonglong2* qq = (const ulonglong2*)s_q;
#pragma unroll 1
            for (int i = 0; i < 5; i++) {
                int p = a_hf * 80 + wid * 5 + i;
                const ulonglong2* pp = (const ulonglong2*)(post + ((size_t)p * B_SZ + b) * PD);
                u64 a0 = 0ull, a1 = 0ull;
#pragma unroll
                for (int s = lane; s < PD / 4; s += 32) {
                    ulonglong2 pv = pp[s];
                    ulonglong2 qv = qq[s];
                    ffma2(a0, pv.x, qv.x);
                    ffma2(a1, pv.y, qv.y);
                }
                float sres = sum2(a0) + sum2(a1);
#pragma unroll
                for (int o = 16; o > 0; o >>= 1)
                    sres += __shfl_xor_sync(0xffffffffu, sres, o);
                if (lane == 0)
                    g_SC[b * PL + p] = (p < pl) ? sres : -1e30f;
            }
        }
        ep++; gsync(ep);

        // ================= Phase 2b: softmax + context (d split) =================
        {
            const int b = a_b;
            if (tid < PL) s_sc[tid] = g_SC[b * PL + tid];
            __syncthreads();
            if (tid < 32) {
                float m = -1e30f;
                for (int p = tid; p < PL; p += 32) m = fmaxf(m, s_sc[p]);
#pragma unroll
                for (int o = 16; o > 0; o >>= 1)
                    m = fmaxf(m, __shfl_xor_sync(0xffffffffu, m, o));
                if (tid == 0) s_st[0] = m;
            }
            __syncthreads();
            if (tid < PL) {
                float e = __expf(s_sc[tid] - s_st[0]);
                s_sc[tid] = e;
                float2 ee = make_float2(e, e);
                s_e2[tid] = *(u64*)&ee;
            }
            __syncthreads();
            if (tid < 32) {
                float s = 0.f;
                for (int p = tid; p < PL; p += 32) s += s_sc[p];
#pragma unroll
                for (int o = 16; o > 0; o >>= 1)
                    s += __shfl_xor_sync(0xffffffffu, s, o);
                if (tid == 0) s_st[1] = 1.f / s;
            }
            __syncthreads();
            if (tid < 128) {
                int dp = a_hf * 128 + tid;
                const u64* pb = (const u64*)post + (size_t)b * (PD / 2) + dp;
                u64 c0 = 0ull, c1 = 0ull;
#pragma unroll 4
                for (int p = 0; p < PL; p += 2) {
                    ffma2(c0, s_e2[p],     pb[(size_t)p * (B_SZ * PD / 2)]);
                    ffma2(c1, s_e2[p + 1], pb[(size_t)(p + 1) * (B_SZ * PD / 2)]);
                }
                u64 c2;
                asm("add.rn.f32x2 %0, %1, %2;" : "=l"(c2) : "l"(c0), "l"(c1));
                float inv = s_st[1];
                float lo = __int_as_float((unsigned)(c2 & 0xffffffffULL)) * inv;
                float hi = __int_as_float((unsigned)(c2 >> 32)) * inv;
                *(float2*)&g_CTX[(size_t)b * PD + 2 * dp] = make_float2(lo, hi);
            }
        }
        ep++; gsync(ep);

        // ================= Phase 3: GRU gates (bulk-TMA double buffered) =================
        {
            u64 acc[2][3];
#pragma unroll
            for (int p = 0; p < 2; p++)
#pragma unroll
                for (int g = 0; g < 3; g++) acc[p][g] = 0ull;

            for (int ch = 0; ch < 8; ch++) {
                int buf = ch & 1;
                unsigned parity = (ch >> 1) & 1;   // 4 uses/buffer/step, even per step
                mbar_wait(smem_u32 + OFF_MB + buf * 8, parity);

                int part = (ch < 4) ? 1 : 0;
                const float* wbase = (const float*)(smem + OFF_W) + buf * WBUF_F;
                const float* xbase = (const float*)(smem + OFF_X) + buf * XBUF_F
                                     + g_lb * WPAD;
                const int wrow = jt * 4 + j_sub;
#pragma unroll 8
                for (int k16 = 0; k16 < 16; k16++) {
                    const ulonglong2* xp = (const ulonglong2*)(xbase + k16 * 16);
                    ulonglong2 xA = xp[0], xB = xp[1], xC = xp[2], xD = xp[3];
#pragma unroll
                    for (int g = 0; g < 3; g++) {
                        const ulonglong2* wp = (const ulonglong2*)
                            (wbase + (g * 16 + wrow) * WPAD + k16 * 16);
                        ulonglong2 wA = wp[0], wB = wp[1], wC = wp[2], wD = wp[3];
                        ffma2(acc[part][g], wA.x, xA.x);
                        ffma2(acc[part][g], wA.y, xA.y);
                        ffma2(acc[part][g], wB.x, xB.x);
                        ffma2(acc[part][g], wB.y, xB.y);
                        ffma2(acc[part][g], wC.x, xC.x);
                        ffma2(acc[part][g], wC.y, xC.y);
                        ffma2(acc[part][g], wD.x, xD.x);
                        ffma2(acc[part][g], wD.y, xD.y);
                    }
                }
                __syncthreads();          // all threads done reading buf
                if (ch + 2 < 8) {
                    prefetch_bulk(smem, smem_u32, buf, ch + 2, t, wih, whh,
                                  hcur, incoming, g_jbase, g_half, wid, lane);
                }
            }

            // epilogue
            float hp  = hcur[(size_t)g_b * H_DIM + g_j];
            float ir  = sum2(acc[0][0]) + bih[g_j];
            float iz  = sum2(acc[0][1]) + bih[H_DIM + g_j];
            float inn = sum2(acc[0][2]) + bih[2 * H_DIM + g_j];
            float hr  = sum2(acc[1][0]) + bhh[g_j];
            float hz  = sum2(acc[1][1]) + bhh[H_DIM + g_j];
            float hnn = sum2(acc[1][2]) + bhh[2 * H_DIM + g_j];
            float r = 1.f / (1.f + __expf(-(ir + hr)));
            float z = 1.f / (1.f + __expf(-(iz + hz)));
            float n = tanhf(inn + r * hnn);
            float hn = (1.f - z) * n + z * hp;
            if (g_len <= t) hn = 0.f;

            hnext[(size_t)g_b * H_DIM + g_j] = hn;
            out[((size_t)t * B_SZ + g_b) * H_DIM + g_j] = hn;
            if (write_last && t == S_LEN - 1) {
                out[(size_t)S_LEN * B_SZ * H_DIM + (size_t)g_b * H_DIM + g_j] = hn;
            }
        }
        ep++; gsync(ep);
    }
}

// ---------------- launch ----------------
extern "C" void kernel_launch(void* const* d_in, const int* in_sizes, int n_in,
                              void* d_out, int out_size) {
    const float* incoming    = (const float*)d_in[0];
    const float* post        = (const float*)d_in[1];
    const float* h_init      = (const float*)d_in[2];
    const float* wih         = (const float*)d_in[3];
    const float* whh         = (const float*)d_in[4];
    const float* bih         = (const float*)d_in[5];
    const float* bhh         = (const float*)d_in[6];
    const float* wq          = (const float*)d_in[7];
    const float* bq          = (const float*)d_in[8];
    const int*   length      = (const int*)d_in[9];
    const int*   post_length = (const int*)d_in[10];
    float* out = (float*)d_out;

    int write_last = (out_size >= S_LEN * B_SZ * H_DIM + B_SZ * H_DIM) ? 1 : 0;

    cudaFuncSetAttribute(gru_kernel, cudaFuncAttributeMaxDynamicSharedMemorySize,
                         SMEM_SZ);

    pre_kernel<<<B_SZ, 256>>>(h_init);
    gru_kernel<<<NBLK, NTHR, SMEM_SZ>>>(incoming, post, wih, whh, bih, bhh,
                                        wq, bq, length, post_length, out,
                                        write_last);
}